// round 6
// baseline (speedup 1.0000x reference)
#include <cuda_runtime.h>

#define BB 4096
#define TT 64
#define T1 65
#define HH 64
#define PP 50
#define VV 32
#define BT 16
#define NBLK (BB / BT) /* 256 */

#define HDS 66   /* float2 stride per h-row (padded: 4-bank shift/row) */

#define SMEM_FLOATS 24752
#define SMEM_BYTES (SMEM_FLOATS * 4)

// ---- device scratch (static allocations only) ----------------------------
__device__ float g_table[3 * 32 * 64];
__device__ float g_phonb[3 * BB * 64];
__device__ float g_hs[BB * TT * HH];        // 64MB: h_t history for projection
__device__ float g_part2[BB];               // per-proj-block nll partials
__device__ float g_cnt2[BB];
__device__ int   g_cs[BB * T1];
__device__ int   g_flag;

// ---- f32x2 helpers --------------------------------------------------------
__device__ __forceinline__ unsigned long long fma2(unsigned long long a,
                                                   unsigned long long b,
                                                   unsigned long long c) {
    asm("fma.rn.f32x2 %0, %1, %2, %0;" : "+l"(c) : "l"(a), "l"(b));
    return c;
}
__device__ __forceinline__ unsigned long long pack2(float a, float b) {
    unsigned long long d;
    asm("mov.b64 %0, {%1, %2};" : "=l"(d)
        : "r"(__float_as_uint(a)), "r"(__float_as_uint(b)));
    return d;
}
__device__ __forceinline__ unsigned long long dup2(float v) {
    unsigned long long d;
    unsigned int u = __float_as_uint(v);
    asm("mov.b64 %0, {%1, %1};" : "=l"(d) : "r"(u));
    return d;
}
__device__ __forceinline__ void unpack2(unsigned long long d, float& a, float& b) {
    unsigned int x, y;
    asm("mov.b64 {%0, %1}, %2;" : "=r"(x), "=r"(y) : "l"(d));
    a = __uint_as_float(x);
    b = __uint_as_float(y);
}
__device__ __forceinline__ float sigf(float x) {
    float e = __expf(-x);
    return __fdividef(1.f, 1.f + e);
}
__device__ __forceinline__ float tanhfast(float x) {
    float e = __expf(-2.f * x);
    return __fdividef(2.f, 1.f + e) - 1.f;
}

// -------------------------------------------------------------------------
// Kernel 0a: detect char_seq dtype (odd-word OR; 0 <=> int64 storage)
// -------------------------------------------------------------------------
__global__ void detect_kernel(const int* __restrict__ src, int nelem) {
    __shared__ int sh[1024];
    int acc = 0;
    for (int i = threadIdx.x; i < nelem; i += 1024)
        if (i & 1) acc |= src[i];
    sh[threadIdx.x] = acc;
    __syncthreads();
    for (int s = 512; s > 0; s >>= 1) {
        if (threadIdx.x < s) sh[threadIdx.x] |= sh[threadIdx.x + s];
        __syncthreads();
    }
    if (threadIdx.x == 0) g_flag = sh[0];
}

__global__ void convert_kernel(const void* __restrict__ src) {
    int i = blockIdx.x * blockDim.x + threadIdx.x;
    if (i >= BB * T1) return;
    if (g_flag != 0) g_cs[i] = ((const int*)src)[i];
    else             g_cs[i] = (int)((const long long*)src)[i];
}

// -------------------------------------------------------------------------
// Kernel 1: char table  table[g][c][j] = sum_k emb[c][k] * W_gx[k][j]
// -------------------------------------------------------------------------
__global__ void table_kernel(const float* __restrict__ emb,
                             const float* __restrict__ Wrx,
                             const float* __restrict__ Wzx,
                             const float* __restrict__ Whx) {
    int idx = blockIdx.x * blockDim.x + threadIdx.x;
    if (idx >= 3 * 32 * 64) return;
    int g = idx >> 11;
    int rem = idx & 2047;
    int c = rem >> 6;
    int j = rem & 63;
    const float* W = (g == 0) ? Wrx : ((g == 1) ? Wzx : Whx);
    const float* e = emb + c * HH;
    float acc = 0.f;
#pragma unroll
    for (int k = 0; k < HH; k++) acc = fmaf(e[k], W[k * HH + j], acc);
    g_table[idx] = acc;
}

// -------------------------------------------------------------------------
// Kernel 2: phon part (f32x2 over j-pairs)
// -------------------------------------------------------------------------
__global__ void phonb_kernel(const float* __restrict__ phon,
                             const float* __restrict__ Wrx,
                             const float* __restrict__ Wzx,
                             const float* __restrict__ Whx,
                             const float* __restrict__ brx,
                             const float* __restrict__ brh,
                             const float* __restrict__ bzx,
                             const float* __restrict__ bzh,
                             const float* __restrict__ bhx,
                             const float* __restrict__ bhh) {
    int idx = blockIdx.x * blockDim.x + threadIdx.x;
    if (idx >= 3 * BB * 32) return;
    int g = idx / (BB * 32);
    int rem = idx - g * (BB * 32);
    int b = rem >> 5;
    int jp = rem & 31;
    const float* W  = (g == 0) ? Wrx : ((g == 1) ? Wzx : Whx);
    const float* bx = (g == 0) ? brx : ((g == 1) ? bzx : bhx);
    const float* bh = (g == 0) ? brh : ((g == 1) ? bzh : bhh);
    float2 x2 = *(const float2*)&bx[jp * 2];
    float2 h2 = *(const float2*)&bh[jp * 2];
    unsigned long long acc = pack2(x2.x + h2.x, x2.y + h2.y);
    const float* ph = phon + b * PP;
#pragma unroll
    for (int p = 0; p < PP; p++) {
        unsigned long long d = dup2(ph[p]);
        unsigned long long w = *(const unsigned long long*)&W[(HH + p) * HH + jp * 2];
        acc = fma2(d, w, acc);
    }
    float a0, a1;
    unpack2(acc, a0, a1);
    *(float2*)&g_phonb[g * (BB * 64) + b * 64 + jp * 2] = make_float2(a0, a1);
}

// -------------------------------------------------------------------------
// Kernel 3: persistent fused GRU recurrence (gates + candidate only).
//   16 rows/block, 256 threads. f32x2 everywhere. h streamed to g_hs.
//   Mapping: rp = tid&7 (2 rows: 2rp,2rp+1), q = tid>>3 (0..31).
//     Pass A: cols gA*64 + 4*(q&15) .. +3  (gA = q>>4; warps 0-3 r, 4-7 z)
//     Pass B: cols 2q, 2q+1
// -------------------------------------------------------------------------
__global__ __launch_bounds__(256, 2)
void gru_kernel(const float* __restrict__ Wrh,
                const float* __restrict__ Wzh,
                const float* __restrict__ Whh) {
    extern __shared__ float sm[];
    float* sWa  = sm;            // [64][128] (r|z), k-major
    float* sWh  = sm + 8192;     // [64][64]
    float* sTab = sm + 12288;    // [3][32][64]
    float* sHd  = sm + 18432;    // float2[16][66] : (h,h) dup, padded
    float* sRHd = sm + 20544;    // float2[16][66] : (r*h, r*h) dup
    float* sZ   = sm + 22656;    // [16][64]
    int*   sCS  = (int*)(sm + 23680); // [16][65]

    const int tid = threadIdx.x;
    const int b0  = blockIdx.x * BT;

    // cooperative init
    for (int i = tid; i < 8192; i += 256) {
        int k = i >> 7, j = i & 127;
        sWa[i] = (j < 64) ? Wrh[k * 64 + j] : Wzh[k * 64 + (j - 64)];
    }
    for (int i = tid; i < 4096; i += 256) sWh[i] = Whh[i];
    for (int i = tid; i < 6144; i += 256) sTab[i] = g_table[i];
    for (int i = tid; i < BT * T1; i += 256) {
        int r = i / T1, t = i - r * T1;
        sCS[i] = g_cs[(b0 + r) * T1 + t];
    }
    for (int i = tid; i < 2 * BT * HDS; i += 256) sHd[i] = 0.f;

    const int rp = tid & 7;
    const int q  = tid >> 3;
    const int row0 = 2 * rp, row1 = row0 + 1;
    const int gA = q >> 4;            // 0: r-gate, 1: z-gate (uniform per warp)
    const int jj = (q & 15) * 4;      // pass-A col base within gate
    const int cB = 2 * q;             // pass-B col base

    float4 pbA0 = *(const float4*)&g_phonb[gA * (BB * 64) + (b0 + row0) * 64 + jj];
    float4 pbA1 = *(const float4*)&g_phonb[gA * (BB * 64) + (b0 + row1) * 64 + jj];
    float2 pbB0 = *(const float2*)&g_phonb[2 * (BB * 64) + (b0 + row0) * 64 + cB];
    float2 pbB1 = *(const float2*)&g_phonb[2 * (BB * 64) + (b0 + row1) * 64 + cB];

    const float* hd0 = sHd + row0 * (2 * HDS);
    const float* hd1 = sHd + row1 * (2 * HDS);
    const float* rd0 = sRHd + row0 * (2 * HDS);
    const float* rd1 = sRHd + row1 * (2 * HDS);
    const float* wbA = sWa + gA * 64 + jj;
    const float* wbB = sWh + cB;

    __syncthreads();

#pragma unroll 1
    for (int t = 0; t < TT; t++) {
        const int c0 = sCS[row0 * T1 + t];
        const int c1 = sCS[row1 * T1 + t];

        // ---------------- Pass A: r,z gates ------------------------------
        unsigned long long a00 = 0, a01 = 0, a10 = 0, a11 = 0;
#pragma unroll
        for (int k4 = 0; k4 < 64; k4 += 4) {
            ulonglong2 d0a = *(const ulonglong2*)(hd0 + k4 * 2);
            ulonglong2 d0b = *(const ulonglong2*)(hd0 + k4 * 2 + 4);
            ulonglong2 d1a = *(const ulonglong2*)(hd1 + k4 * 2);
            ulonglong2 d1b = *(const ulonglong2*)(hd1 + k4 * 2 + 4);
            ulonglong2 w0 = *(const ulonglong2*)(wbA + (k4 + 0) * 128);
            ulonglong2 w1 = *(const ulonglong2*)(wbA + (k4 + 1) * 128);
            ulonglong2 w2 = *(const ulonglong2*)(wbA + (k4 + 2) * 128);
            ulonglong2 w3 = *(const ulonglong2*)(wbA + (k4 + 3) * 128);
            a00 = fma2(d0a.x, w0.x, a00); a01 = fma2(d0a.x, w0.y, a01);
            a10 = fma2(d1a.x, w0.x, a10); a11 = fma2(d1a.x, w0.y, a11);
            a00 = fma2(d0a.y, w1.x, a00); a01 = fma2(d0a.y, w1.y, a01);
            a10 = fma2(d1a.y, w1.x, a10); a11 = fma2(d1a.y, w1.y, a11);
            a00 = fma2(d0b.x, w2.x, a00); a01 = fma2(d0b.x, w2.y, a01);
            a10 = fma2(d1b.x, w2.x, a10); a11 = fma2(d1b.x, w2.y, a11);
            a00 = fma2(d0b.y, w3.x, a00); a01 = fma2(d0b.y, w3.y, a01);
            a10 = fma2(d1b.y, w3.x, a10); a11 = fma2(d1b.y, w3.y, a11);
        }
        {
            float p0, p1, p2, p3, p4, p5, p6, p7;
            unpack2(a00, p0, p1); unpack2(a01, p2, p3);
            unpack2(a10, p4, p5); unpack2(a11, p6, p7);
            float4 t0 = *(const float4*)&sTab[gA * 2048 + c0 * 64 + jj];
            float4 t1 = *(const float4*)&sTab[gA * 2048 + c1 * 64 + jj];
            float g0 = sigf(p0 + t0.x + pbA0.x);
            float g1 = sigf(p1 + t0.y + pbA0.y);
            float g2 = sigf(p2 + t0.z + pbA0.z);
            float g3 = sigf(p3 + t0.w + pbA0.w);
            float g4 = sigf(p4 + t1.x + pbA1.x);
            float g5 = sigf(p5 + t1.y + pbA1.y);
            float g6 = sigf(p6 + t1.z + pbA1.z);
            float g7 = sigf(p7 + t1.w + pbA1.w);
            if (gA == 0) {
                float4 hA = *(const float4*)(hd0 + jj * 2);
                float4 hB = *(const float4*)(hd0 + jj * 2 + 4);
                float4 hC = *(const float4*)(hd1 + jj * 2);
                float4 hD = *(const float4*)(hd1 + jj * 2 + 4);
                float r0 = g0 * hA.x, r1 = g1 * hA.z, r2 = g2 * hB.x, r3 = g3 * hB.z;
                float r4 = g4 * hC.x, r5 = g5 * hC.z, r6 = g6 * hD.x, r7 = g7 * hD.z;
                *(float4*)(sRHd + row0 * (2 * HDS) + jj * 2)     = make_float4(r0, r0, r1, r1);
                *(float4*)(sRHd + row0 * (2 * HDS) + jj * 2 + 4) = make_float4(r2, r2, r3, r3);
                *(float4*)(sRHd + row1 * (2 * HDS) + jj * 2)     = make_float4(r4, r4, r5, r5);
                *(float4*)(sRHd + row1 * (2 * HDS) + jj * 2 + 4) = make_float4(r6, r6, r7, r7);
            } else {
                *(float4*)&sZ[row0 * 64 + jj] = make_float4(g0, g1, g2, g3);
                *(float4*)&sZ[row1 * 64 + jj] = make_float4(g4, g5, g6, g7);
            }
        }
        __syncthreads();

        // ---------------- Pass B: candidate + h update --------------------
        unsigned long long bA = 0, bBv = 0;
#pragma unroll
        for (int k4 = 0; k4 < 64; k4 += 4) {
            ulonglong2 r0a = *(const ulonglong2*)(rd0 + k4 * 2);
            ulonglong2 r0b = *(const ulonglong2*)(rd0 + k4 * 2 + 4);
            ulonglong2 r1a = *(const ulonglong2*)(rd1 + k4 * 2);
            ulonglong2 r1b = *(const ulonglong2*)(rd1 + k4 * 2 + 4);
            unsigned long long w0 = *(const unsigned long long*)(wbB + (k4 + 0) * 64);
            unsigned long long w1 = *(const unsigned long long*)(wbB + (k4 + 1) * 64);
            unsigned long long w2 = *(const unsigned long long*)(wbB + (k4 + 2) * 64);
            unsigned long long w3 = *(const unsigned long long*)(wbB + (k4 + 3) * 64);
            bA  = fma2(r0a.x, w0, bA);  bBv = fma2(r1a.x, w0, bBv);
            bA  = fma2(r0a.y, w1, bA);  bBv = fma2(r1a.y, w1, bBv);
            bA  = fma2(r0b.x, w2, bA);  bBv = fma2(r1b.x, w2, bBv);
            bA  = fma2(r0b.y, w3, bA);  bBv = fma2(r1b.y, w3, bBv);
        }
        {
            float x00, x01, x10, x11;
            unpack2(bA, x00, x01);
            unpack2(bBv, x10, x11);
            float2 tb0 = *(const float2*)&sTab[4096 + c0 * 64 + cB];
            float2 tb1 = *(const float2*)&sTab[4096 + c1 * 64 + cB];
            float cv00 = tanhfast(x00 + tb0.x + pbB0.x);
            float cv01 = tanhfast(x01 + tb0.y + pbB0.y);
            float cv10 = tanhfast(x10 + tb1.x + pbB1.x);
            float cv11 = tanhfast(x11 + tb1.y + pbB1.y);
            float2 z0 = *(const float2*)&sZ[row0 * 64 + cB];
            float2 z1 = *(const float2*)&sZ[row1 * 64 + cB];
            float4 h0d = *(const float4*)(hd0 + cB * 2);  // (h0,h0,h1,h1)
            float4 h1d = *(const float4*)(hd1 + cB * 2);
            float hn00 = fmaf(z0.x, cv00 - h0d.x, h0d.x);
            float hn01 = fmaf(z0.y, cv01 - h0d.z, h0d.z);
            float hn10 = fmaf(z1.x, cv10 - h1d.x, h1d.x);
            float hn11 = fmaf(z1.y, cv11 - h1d.z, h1d.z);
            *(float4*)(sHd + row0 * (2 * HDS) + cB * 2) = make_float4(hn00, hn00, hn01, hn01);
            *(float4*)(sHd + row1 * (2 * HDS) + cB * 2) = make_float4(hn10, hn10, hn11, hn11);
            *(float2*)&g_hs[((b0 + row0) * TT + t) * HH + cB] = make_float2(hn00, hn01);
            *(float2*)&g_hs[((b0 + row1) * TT + t) * HH + cB] = make_float2(hn10, hn11);
        }
        __syncthreads();
    }
}

// -------------------------------------------------------------------------
// Kernel 4: projection + log-softmax + NLL (fully parallel, f32x2).
//   block = 64 (b,t)-rows, 256 threads; warp w handles rows 8w..8w+7 as
//   4 row-pairs (half-warps), 2 vocab cols per lane.
// -------------------------------------------------------------------------
__global__ __launch_bounds__(256, 4)
void proj_kernel(const float* __restrict__ Wproj,
                 const float* __restrict__ bproj,
                 float* __restrict__ out) {
    __shared__ float sWp[64 * 32];
    __shared__ float sHdp[64 * 64 * 2];   // (h,h) dup per scalar
    __shared__ float sRed[16];
    const int tid = threadIdx.x;
    const long long R0 = (long long)blockIdx.x * 64;

    for (int i = tid; i < 2048; i += 256) sWp[i] = Wproj[i];
    const float* hsrc = g_hs + R0 * HH;
#pragma unroll
    for (int j = 0; j < 16; j++) {
        int s = tid + j * 256;
        float v = hsrc[s];
        *(float2*)&sHdp[s * 2] = make_float2(v, v);
    }
    __syncthreads();

    const int lane = tid & 31, w = tid >> 5;
    const int half = lane >> 4;
    const int vp = lane & 15;
    unsigned long long bp2;
    {
        float2 bb = *(const float2*)&bproj[vp * 2];
        bp2 = pack2(bb.x, bb.y);
    }
    float nll = 0.f, cnt = 0.f;
#pragma unroll
    for (int p = 0; p < 4; p++) {
        int r = w * 8 + p * 2 + half;
        long long R = R0 + r;
        int b = (int)(R >> 6), t = (int)(R & 63);
        unsigned long long acc = bp2;
        const float* hd = &sHdp[r * 128];
#pragma unroll
        for (int k = 0; k < 64; k++) {
            unsigned long long d  = *(const unsigned long long*)(hd + k * 2);
            unsigned long long wv = *(const unsigned long long*)&sWp[k * 32 + vp * 2];
            acc = fma2(d, wv, acc);
        }
        float lo, hi;
        unpack2(acc, lo, hi);
        *(float2*)&out[R * VV + vp * 2] = make_float2(lo, hi);
        int tgt = g_cs[b * T1 + t + 1];
        float m = fmaxf(lo, hi);
#pragma unroll
        for (int o = 8; o > 0; o >>= 1)
            m = fmaxf(m, __shfl_xor_sync(0xffffffffu, m, o));
        float s = __expf(lo - m) + __expf(hi - m);
#pragma unroll
        for (int o = 8; o > 0; o >>= 1)
            s += __shfl_xor_sync(0xffffffffu, s, o);
        float pick = (tgt & 1) ? hi : lo;
        float lt = __shfl_sync(0xffffffffu, pick, (half << 4) + (tgt >> 1));
        if (vp == 0 && tgt != 0) {
            nll += m + __logf(s) - lt;
            cnt += 1.f;
        }
    }
    nll += __shfl_xor_sync(0xffffffffu, nll, 16);
    cnt += __shfl_xor_sync(0xffffffffu, cnt, 16);
    if (lane == 0) { sRed[w] = nll; sRed[8 + w] = cnt; }
    __syncthreads();
    if (tid == 0) {
        float a = 0.f, c = 0.f;
#pragma unroll
        for (int i = 0; i < 8; i++) { a += sRed[i]; c += sRed[8 + i]; }
        g_part2[blockIdx.x] = a;
        g_cnt2[blockIdx.x] = c;
    }
}

// -------------------------------------------------------------------------
// Kernel 5: final deterministic loss reduction over 4096 partials
// -------------------------------------------------------------------------
__global__ void loss2_kernel(float* __restrict__ out, long long out_size) {
    __shared__ float sa[1024], sc[1024];
    int tid = threadIdx.x;
    float a = 0.f, c = 0.f;
    for (int i = tid; i < BB; i += 1024) { a += g_part2[i]; c += g_cnt2[i]; }
    sa[tid] = a; sc[tid] = c;
    __syncthreads();
    for (int s = 512; s > 0; s >>= 1) {
        if (tid < s) { sa[tid] += sa[tid + s]; sc[tid] += sc[tid + s]; }
        __syncthreads();
    }
    if (tid == 0 && out_size > (long long)BB * TT * VV)
        out[out_size - 1] = sa[0] / fmaxf(sc[0], 1.f);
}

// -------------------------------------------------------------------------
extern "C" void kernel_launch(void* const* d_in, const int* in_sizes, int n_in,
                              void* d_out, int out_size) {
    const float* phon  = (const float*)d_in[0];
    const void*  cs    = d_in[1];
    const float* emb   = (const float*)d_in[2];
    const float* Wrx   = (const float*)d_in[3];
    const float* brx   = (const float*)d_in[4];
    const float* Wrh   = (const float*)d_in[5];
    const float* brh   = (const float*)d_in[6];
    const float* Wzx   = (const float*)d_in[7];
    const float* bzx   = (const float*)d_in[8];
    const float* Wzh   = (const float*)d_in[9];
    const float* bzh   = (const float*)d_in[10];
    const float* Whx   = (const float*)d_in[11];
    const float* bhx   = (const float*)d_in[12];
    const float* Whh   = (const float*)d_in[13];
    const float* bhh   = (const float*)d_in[14];
    const float* Wproj = (const float*)d_in[15];
    const float* bproj = (const float*)d_in[16];
    float* out = (float*)d_out;

    (void)cudaFuncSetAttribute(gru_kernel,
                               cudaFuncAttributeMaxDynamicSharedMemorySize,
                               SMEM_BYTES);

    detect_kernel<<<1, 1024>>>((const int*)cs, BB * T1);
    convert_kernel<<<(BB * T1 + 255) / 256, 256>>>(cs);
    table_kernel<<<24, 256>>>(emb, Wrx, Wzx, Whx);
    phonb_kernel<<<(3 * BB * 32 + 255) / 256, 256>>>(phon, Wrx, Wzx, Whx,
                                                     brx, brh, bzx, bzh, bhx, bhh);
    gru_kernel<<<NBLK, 256, SMEM_BYTES>>>(Wrh, Wzh, Whh);
    proj_kernel<<<BB, 256>>>(Wproj, bproj, out);
    loss2_kernel<<<1, 1024>>>(out, (long long)out_size);
}

// round 8
// speedup vs baseline: 1.9178x; 1.9178x over previous
#include <cuda_runtime.h>

#define BB 4096
#define TT 64
#define T1 65
#define HH 64
#define PP 50
#define VV 32
#define BT 16
#define NBLK (BB / BT) /* 256 */

#define SMEM_FLOATS 22544
#define SMEM_BYTES (SMEM_FLOATS * 4)

// ---- device scratch (static allocations only) ----------------------------
__device__ float g_table[3 * 32 * 64];
__device__ float g_phonb[3 * BB * 64];
__device__ float g_hs[BB * TT * HH];        // 64MB: h_t history for projection
__device__ float g_part2[BB];
__device__ float g_cnt2[BB];
__device__ int   g_cs[BB * T1];
__device__ int   g_flag;

// ---- helpers --------------------------------------------------------------
__device__ __forceinline__ unsigned long long fma2(unsigned long long a,
                                                   unsigned long long b,
                                                   unsigned long long c) {
    asm("fma.rn.f32x2 %0, %1, %2, %0;" : "+l"(c) : "l"(a), "l"(b));
    return c;
}
__device__ __forceinline__ unsigned long long pack2(float a, float b) {
    unsigned long long d;
    asm("mov.b64 %0, {%1, %2};" : "=l"(d)
        : "r"(__float_as_uint(a)), "r"(__float_as_uint(b)));
    return d;
}
__device__ __forceinline__ unsigned long long dup2(float v) {
    unsigned long long d;
    unsigned int u = __float_as_uint(v);
    asm("mov.b64 %0, {%1, %1};" : "=l"(d) : "r"(u));
    return d;
}
__device__ __forceinline__ void unpack2(unsigned long long d, float& a, float& b) {
    unsigned int x, y;
    asm("mov.b64 {%0, %1}, %2;" : "=r"(x), "=r"(y) : "l"(d));
    a = __uint_as_float(x);
    b = __uint_as_float(y);
}
__device__ __forceinline__ float sigf(float x) {
    float e = __expf(-x);
    return __fdividef(1.f, 1.f + e);
}
__device__ __forceinline__ float tanhfast(float x) {
    float e = __expf(-2.f * x);
    return __fdividef(2.f, 1.f + e) - 1.f;
}

// -------------------------------------------------------------------------
// Kernel 0a: detect char_seq dtype (odd-word OR; 0 <=> int64 storage)
// -------------------------------------------------------------------------
__global__ void detect_kernel(const int* __restrict__ src, int nelem) {
    __shared__ int sh[1024];
    int acc = 0;
    for (int i = threadIdx.x; i < nelem; i += 1024)
        if (i & 1) acc |= src[i];
    sh[threadIdx.x] = acc;
    __syncthreads();
    for (int s = 512; s > 0; s >>= 1) {
        if (threadIdx.x < s) sh[threadIdx.x] |= sh[threadIdx.x + s];
        __syncthreads();
    }
    if (threadIdx.x == 0) g_flag = sh[0];
}

__global__ void convert_kernel(const void* __restrict__ src) {
    int i = blockIdx.x * blockDim.x + threadIdx.x;
    if (i >= BB * T1) return;
    if (g_flag != 0) g_cs[i] = ((const int*)src)[i];
    else             g_cs[i] = (int)((const long long*)src)[i];
}

// -------------------------------------------------------------------------
// Kernel 1: char table  table[g][c][j] = sum_k emb[c][k] * W_gx[k][j]
// -------------------------------------------------------------------------
__global__ void table_kernel(const float* __restrict__ emb,
                             const float* __restrict__ Wrx,
                             const float* __restrict__ Wzx,
                             const float* __restrict__ Whx) {
    int idx = blockIdx.x * blockDim.x + threadIdx.x;
    if (idx >= 3 * 32 * 64) return;
    int g = idx >> 11;
    int rem = idx & 2047;
    int c = rem >> 6;
    int j = rem & 63;
    const float* W = (g == 0) ? Wrx : ((g == 1) ? Wzx : Whx);
    const float* e = emb + c * HH;
    float acc = 0.f;
#pragma unroll
    for (int k = 0; k < HH; k++) acc = fmaf(e[k], W[k * HH + j], acc);
    g_table[idx] = acc;
}

// -------------------------------------------------------------------------
// Kernel 2: phon part (f32x2 over j-pairs) — measured 11.3us
// -------------------------------------------------------------------------
__global__ void phonb_kernel(const float* __restrict__ phon,
                             const float* __restrict__ Wrx,
                             const float* __restrict__ Wzx,
                             const float* __restrict__ Whx,
                             const float* __restrict__ brx,
                             const float* __restrict__ brh,
                             const float* __restrict__ bzx,
                             const float* __restrict__ bzh,
                             const float* __restrict__ bhx,
                             const float* __restrict__ bhh) {
    int idx = blockIdx.x * blockDim.x + threadIdx.x;
    if (idx >= 3 * BB * 32) return;
    int g = idx / (BB * 32);
    int rem = idx - g * (BB * 32);
    int b = rem >> 5;
    int jp = rem & 31;
    const float* W  = (g == 0) ? Wrx : ((g == 1) ? Wzx : Whx);
    const float* bx = (g == 0) ? brx : ((g == 1) ? bzx : bhx);
    const float* bh = (g == 0) ? brh : ((g == 1) ? bzh : bhh);
    float2 x2 = *(const float2*)&bx[jp * 2];
    float2 h2 = *(const float2*)&bh[jp * 2];
    unsigned long long acc = pack2(x2.x + h2.x, x2.y + h2.y);
    const float* ph = phon + b * PP;
#pragma unroll
    for (int p = 0; p < PP; p++) {
        unsigned long long d = dup2(ph[p]);
        unsigned long long w = *(const unsigned long long*)&W[(HH + p) * HH + jp * 2];
        acc = fma2(d, w, acc);
    }
    float a0, a1;
    unpack2(acc, a0, a1);
    *(float2*)&g_phonb[g * (BB * 64) + b * 64 + jp * 2] = make_float2(a0, a1);
}

// -------------------------------------------------------------------------
// Kernel 3: persistent GRU recurrence — round-4 structure (scalar FFMA),
//   pass C removed; h streamed to g_hs. 16 rows/block, 256 threads.
// -------------------------------------------------------------------------
__global__ __launch_bounds__(256, 2)
void gru_kernel(const float* __restrict__ Wrh,
                const float* __restrict__ Wzh,
                const float* __restrict__ Whh) {
    extern __shared__ float sm[];
    float* sWa  = sm;            // [64][128]: W_rh | W_zh, k-major
    float* sWh  = sm + 8192;     // [64][64]
    float* sTab = sm + 12288;    // [3][32][64]
    float* sH   = sm + 18432;    // [16][64]
    float* sRH  = sm + 19456;    // [16][64]  r*h
    float* sZ   = sm + 20480;    // [16][64]  z
    int*   sCS  = (int*)(sm + 21504); // [16][65]

    const int tid = threadIdx.x;
    const int b0 = blockIdx.x * BT;

    // cooperative init
    for (int i = tid; i < 8192; i += 256) {
        int k = i >> 7, j = i & 127;
        sWa[i] = (j < 64) ? Wrh[k * 64 + j] : Wzh[k * 64 + (j - 64)];
    }
    for (int i = tid; i < 4096; i += 256) sWh[i] = Whh[i];
    for (int i = tid; i < 6144; i += 256) sTab[i] = g_table[i];
    for (int i = tid; i < BT * T1; i += 256) {
        int r = i / T1, t = i - r * T1;
        sCS[i] = g_cs[(b0 + r) * T1 + t];
    }
    for (int i = tid; i < BT * 64; i += 256) sH[i] = 0.f;

    // thread mappings (round-4)
    const int rq = tid >> 6;         // 0..3 -> rows 4*rq..4*rq+3
    const int cg = tid & 63;         // 0..63
    const int j0 = cg << 1;          // 0..126 (pass A col pair over [r|z])
    const int gA = (j0 >= 64) ? 1 : 0;
    const int jjA = j0 & 63;

    float pbA[4][2], pbB[4];
#pragma unroll
    for (int r = 0; r < 4; r++) {
        int base = gA * (BB * 64) + (b0 + 4 * rq + r) * 64 + jjA;
        pbA[r][0] = g_phonb[base];
        pbA[r][1] = g_phonb[base + 1];
        pbB[r] = g_phonb[2 * (BB * 64) + (b0 + 4 * rq + r) * 64 + cg];
    }

    __syncthreads();

#pragma unroll 1
    for (int t = 0; t < TT; t++) {
        // ---------------- Pass A: r,z gates:  h @ [W_rh|W_zh] -------------
        float acc[4][2];
#pragma unroll
        for (int r = 0; r < 4; r++) { acc[r][0] = 0.f; acc[r][1] = 0.f; }
#pragma unroll
        for (int k4 = 0; k4 < 64; k4 += 4) {
            float hr[4][4];
#pragma unroll
            for (int r = 0; r < 4; r++) {
                float4 hv = *(const float4*)&sH[(4 * rq + r) * 64 + k4];
                hr[r][0] = hv.x; hr[r][1] = hv.y; hr[r][2] = hv.z; hr[r][3] = hv.w;
            }
#pragma unroll
            for (int kk = 0; kk < 4; kk++) {
                float2 w = *(const float2*)&sWa[(k4 + kk) * 128 + j0];
#pragma unroll
                for (int r = 0; r < 4; r++) {
                    acc[r][0] = fmaf(hr[r][kk], w.x, acc[r][0]);
                    acc[r][1] = fmaf(hr[r][kk], w.y, acc[r][1]);
                }
            }
        }
        int cc[4];
#pragma unroll
        for (int r = 0; r < 4; r++) cc[r] = sCS[(4 * rq + r) * T1 + t];
        const float* tg_ = sTab + gA * 2048;
#pragma unroll
        for (int r = 0; r < 4; r++) {
            float2 tv = *(const float2*)&tg_[cc[r] * 64 + jjA];
            float p0 = acc[r][0] + tv.x + pbA[r][0];
            float p1 = acc[r][1] + tv.y + pbA[r][1];
            float g0 = sigf(p0);
            float g1 = sigf(p1);
            if (gA == 0) {
                float2 ho = *(const float2*)&sH[(4 * rq + r) * 64 + j0];
                float2 o; o.x = g0 * ho.x; o.y = g1 * ho.y;
                *(float2*)&sRH[(4 * rq + r) * 64 + j0] = o;
            } else {
                float2 o; o.x = g0; o.y = g1;
                *(float2*)&sZ[(4 * rq + r) * 64 + jjA] = o;
            }
        }
        __syncthreads();

        // ---------------- Pass B: candidate + h update --------------------
        float accB[4] = {0.f, 0.f, 0.f, 0.f};
#pragma unroll
        for (int k4 = 0; k4 < 64; k4 += 4) {
            float rr[4][4];
#pragma unroll
            for (int r = 0; r < 4; r++) {
                float4 rv = *(const float4*)&sRH[(4 * rq + r) * 64 + k4];
                rr[r][0] = rv.x; rr[r][1] = rv.y; rr[r][2] = rv.z; rr[r][3] = rv.w;
            }
#pragma unroll
            for (int kk = 0; kk < 4; kk++) {
                float w = sWh[(k4 + kk) * 64 + cg];
#pragma unroll
                for (int r = 0; r < 4; r++)
                    accB[r] = fmaf(rr[r][kk], w, accB[r]);
            }
        }
#pragma unroll
        for (int r = 0; r < 4; r++) {
            float pre = accB[r] + sTab[4096 + cc[r] * 64 + cg] + pbB[r];
            float cv = tanhfast(pre);
            int hi = (4 * rq + r) * 64 + cg;
            float z = sZ[hi];
            float ho = sH[hi];
            float hn = fmaf(z, cv - ho, ho);   // (1-z)h + z c
            sH[hi] = hn;
            g_hs[((b0 + 4 * rq + r) * TT + t) * HH + cg] = hn;
        }
        __syncthreads();
    }
}

// -------------------------------------------------------------------------
// Kernel 4: projection + log-softmax + NLL (fully parallel, f32x2).
//   block = 64 (b,t)-rows, 256 threads (validated in round 6).
// -------------------------------------------------------------------------
__global__ __launch_bounds__(256, 4)
void proj_kernel(const float* __restrict__ Wproj,
                 const float* __restrict__ bproj,
                 float* __restrict__ out) {
    __shared__ float sWp[64 * 32];
    __shared__ float sHdp[64 * 64 * 2];   // (h,h) dup per scalar
    __shared__ float sRed[16];
    const int tid = threadIdx.x;
    const long long R0 = (long long)blockIdx.x * 64;

    for (int i = tid; i < 2048; i += 256) sWp[i] = Wproj[i];
    const float* hsrc = g_hs + R0 * HH;
#pragma unroll
    for (int j = 0; j < 16; j++) {
        int s = tid + j * 256;
        float v = hsrc[s];
        *(float2*)&sHdp[s * 2] = make_float2(v, v);
    }
    __syncthreads();

    const int lane = tid & 31, w = tid >> 5;
    const int half = lane >> 4;
    const int vp = lane & 15;
    unsigned long long bp2;
    {
        float2 bb = *(const float2*)&bproj[vp * 2];
        bp2 = pack2(bb.x, bb.y);
    }
    float nll = 0.f, cnt = 0.f;
#pragma unroll
    for (int p = 0; p < 4; p++) {
        int r = w * 8 + p * 2 + half;
        long long R = R0 + r;
        int b = (int)(R >> 6), t = (int)(R & 63);
        unsigned long long acc = bp2;
        const float* hd = &sHdp[r * 128];
#pragma unroll
        for (int k = 0; k < 64; k++) {
            unsigned long long d  = *(const unsigned long long*)(hd + k * 2);
            unsigned long long wv = *(const unsigned long long*)&sWp[k * 32 + vp * 2];
            acc = fma2(d, wv, acc);
        }
        float lo, hi;
        unpack2(acc, lo, hi);
        *(float2*)&out[R * VV + vp * 2] = make_float2(lo, hi);
        int tgt = g_cs[b * T1 + t + 1];
        float m = fmaxf(lo, hi);
#pragma unroll
        for (int o = 8; o > 0; o >>= 1)
            m = fmaxf(m, __shfl_xor_sync(0xffffffffu, m, o));
        float s = __expf(lo - m) + __expf(hi - m);
#pragma unroll
        for (int o = 8; o > 0; o >>= 1)
            s += __shfl_xor_sync(0xffffffffu, s, o);
        float pick = (tgt & 1) ? hi : lo;
        float lt = __shfl_sync(0xffffffffu, pick, (half << 4) + (tgt >> 1));
        if (vp == 0 && tgt != 0) {
            nll += m + __logf(s) - lt;
            cnt += 1.f;
        }
    }
    nll += __shfl_xor_sync(0xffffffffu, nll, 16);
    cnt += __shfl_xor_sync(0xffffffffu, cnt, 16);
    if (lane == 0) { sRed[w] = nll; sRed[8 + w] = cnt; }
    __syncthreads();
    if (tid == 0) {
        float a = 0.f, c = 0.f;
#pragma unroll
        for (int i = 0; i < 8; i++) { a += sRed[i]; c += sRed[8 + i]; }
        g_part2[blockIdx.x] = a;
        g_cnt2[blockIdx.x] = c;
    }
}

// -------------------------------------------------------------------------
// Kernel 5: final deterministic loss reduction over 4096 partials
// -------------------------------------------------------------------------
__global__ void loss2_kernel(float* __restrict__ out, long long out_size) {
    __shared__ float sa[1024], sc[1024];
    int tid = threadIdx.x;
    float a = 0.f, c = 0.f;
    for (int i = tid; i < BB; i += 1024) { a += g_part2[i]; c += g_cnt2[i]; }
    sa[tid] = a; sc[tid] = c;
    __syncthreads();
    for (int s = 512; s > 0; s >>= 1) {
        if (tid < s) { sa[tid] += sa[tid + s]; sc[tid] += sc[tid + s]; }
        __syncthreads();
    }
    if (tid == 0 && out_size > (long long)BB * TT * VV)
        out[out_size - 1] = sa[0] / fmaxf(sc[0], 1.f);
}

// -------------------------------------------------------------------------
extern "C" void kernel_launch(void* const* d_in, const int* in_sizes, int n_in,
                              void* d_out, int out_size) {
    const float* phon  = (const float*)d_in[0];
    const void*  cs    = d_in[1];
    const float* emb   = (const float*)d_in[2];
    const float* Wrx   = (const float*)d_in[3];
    const float* brx   = (const float*)d_in[4];
    const float* Wrh   = (const float*)d_in[5];
    const float* brh   = (const float*)d_in[6];
    const float* Wzx   = (const float*)d_in[7];
    const float* bzx   = (const float*)d_in[8];
    const float* Wzh   = (const float*)d_in[9];
    const float* bzh   = (const float*)d_in[10];
    const float* Whx   = (const float*)d_in[11];
    const float* bhx   = (const float*)d_in[12];
    const float* Whh   = (const float*)d_in[13];
    const float* bhh   = (const float*)d_in[14];
    const float* Wproj = (const float*)d_in[15];
    const float* bproj = (const float*)d_in[16];
    float* out = (float*)d_out;

    (void)cudaFuncSetAttribute(gru_kernel,
                               cudaFuncAttributeMaxDynamicSharedMemorySize,
                               SMEM_BYTES);

    detect_kernel<<<1, 1024>>>((const int*)cs, BB * T1);
    convert_kernel<<<(BB * T1 + 255) / 256, 256>>>(cs);
    table_kernel<<<24, 256>>>(emb, Wrx, Wzx, Whx);
    phonb_kernel<<<(3 * BB * 32 + 255) / 256, 256>>>(phon, Wrx, Wzx, Whx,
                                                     brx, brh, bzx, bzh, bhx, bhh);
    gru_kernel<<<NBLK, 256, SMEM_BYTES>>>(Wrh, Wzh, Whh);
    proj_kernel<<<BB, 256>>>(Wproj, bproj, out);
    loss2_kernel<<<1, 1024>>>(out, (long long)out_size);
}

// round 9
// speedup vs baseline: 2.5004x; 1.3038x over previous
#include <cuda_runtime.h>

#define BB 4096
#define TT 64
#define T1 65
#define HH 64
#define PP 50
#define VV 32
#define BT 16
#define NBLK (BB / BT) /* 256 */

#define SMEM_FLOATS 24608
#define SMEM_BYTES (SMEM_FLOATS * 4)

// scratch (device globals; no allocation allowed)
__device__ float g_table[3 * 32 * 64];
__device__ float g_phonb[3 * BB * 64];
__device__ float g_part[2 * NBLK];
__device__ int   g_cs[BB * T1];
__device__ int   g_flag;

// ---- helpers --------------------------------------------------------------
__device__ __forceinline__ unsigned long long fma2(unsigned long long a,
                                                   unsigned long long b,
                                                   unsigned long long c) {
    asm("fma.rn.f32x2 %0, %1, %2, %0;" : "+l"(c) : "l"(a), "l"(b));
    return c;
}
__device__ __forceinline__ unsigned long long pack2(float a, float b) {
    unsigned long long d;
    asm("mov.b64 %0, {%1, %2};" : "=l"(d)
        : "r"(__float_as_uint(a)), "r"(__float_as_uint(b)));
    return d;
}
__device__ __forceinline__ unsigned long long dup2(float v) {
    unsigned long long d;
    unsigned int u = __float_as_uint(v);
    asm("mov.b64 %0, {%1, %1};" : "=l"(d) : "r"(u));
    return d;
}
__device__ __forceinline__ void unpack2(unsigned long long d, float& a, float& b) {
    unsigned int x, y;
    asm("mov.b64 {%0, %1}, %2;" : "=r"(x), "=r"(y) : "l"(d));
    a = __uint_as_float(x);
    b = __uint_as_float(y);
}
__device__ __forceinline__ float sigf(float x) {
    float e = __expf(-x);
    return __fdividef(1.f, 1.f + e);
}
__device__ __forceinline__ float tanhfast(float x) {
    float e = __expf(-2.f * x);
    return __fdividef(2.f, 1.f + e) - 1.f;
}

// -------------------------------------------------------------------------
// Kernel 0a: detect char_seq dtype (odd-word OR; 0 <=> int64 storage)
// -------------------------------------------------------------------------
__global__ void detect_kernel(const int* __restrict__ src, int nelem) {
    __shared__ int sh[1024];
    int acc = 0;
    for (int i = threadIdx.x; i < nelem; i += 1024)
        if (i & 1) acc |= src[i];
    sh[threadIdx.x] = acc;
    __syncthreads();
    for (int s = 512; s > 0; s >>= 1) {
        if (threadIdx.x < s) sh[threadIdx.x] |= sh[threadIdx.x + s];
        __syncthreads();
    }
    if (threadIdx.x == 0) g_flag = sh[0];
}

__global__ void convert_kernel(const void* __restrict__ src) {
    int i = blockIdx.x * blockDim.x + threadIdx.x;
    if (i >= BB * T1) return;
    if (g_flag != 0) g_cs[i] = ((const int*)src)[i];
    else             g_cs[i] = (int)((const long long*)src)[i];
}

// -------------------------------------------------------------------------
// Kernel 1: char table  table[g][c][j] = sum_k emb[c][k] * W_gx[k][j]
// -------------------------------------------------------------------------
__global__ void table_kernel(const float* __restrict__ emb,
                             const float* __restrict__ Wrx,
                             const float* __restrict__ Wzx,
                             const float* __restrict__ Whx) {
    int idx = blockIdx.x * blockDim.x + threadIdx.x;
    if (idx >= 3 * 32 * 64) return;
    int g = idx >> 11;
    int rem = idx & 2047;
    int c = rem >> 6;
    int j = rem & 63;
    const float* W = (g == 0) ? Wrx : ((g == 1) ? Wzx : Whx);
    const float* e = emb + c * HH;
    float acc = 0.f;
#pragma unroll
    for (int k = 0; k < HH; k++) acc = fmaf(e[k], W[k * HH + j], acc);
    g_table[idx] = acc;
}

// -------------------------------------------------------------------------
// Kernel 2: phon part (f32x2 over j-pairs) — measured fast
// -------------------------------------------------------------------------
__global__ void phonb_kernel(const float* __restrict__ phon,
                             const float* __restrict__ Wrx,
                             const float* __restrict__ Wzx,
                             const float* __restrict__ Whx,
                             const float* __restrict__ brx,
                             const float* __restrict__ brh,
                             const float* __restrict__ bzx,
                             const float* __restrict__ bzh,
                             const float* __restrict__ bhx,
                             const float* __restrict__ bhh) {
    int idx = blockIdx.x * blockDim.x + threadIdx.x;
    if (idx >= 3 * BB * 32) return;
    int g = idx / (BB * 32);
    int rem = idx - g * (BB * 32);
    int b = rem >> 5;
    int jp = rem & 31;
    const float* W  = (g == 0) ? Wrx : ((g == 1) ? Wzx : Whx);
    const float* bx = (g == 0) ? brx : ((g == 1) ? bzx : bhx);
    const float* bh = (g == 0) ? brh : ((g == 1) ? bzh : bhh);
    float2 x2 = *(const float2*)&bx[jp * 2];
    float2 h2 = *(const float2*)&bh[jp * 2];
    unsigned long long acc = pack2(x2.x + h2.x, x2.y + h2.y);
    const float* ph = phon + b * PP;
#pragma unroll
    for (int p = 0; p < PP; p++) {
        unsigned long long d = dup2(ph[p]);
        unsigned long long w = *(const unsigned long long*)&W[(HH + p) * HH + jp * 2];
        acc = fma2(d, w, acc);
    }
    float a0, a1;
    unpack2(acc, a0, a1);
    *(float2*)&g_phonb[g * (BB * 64) + b * 64 + jp * 2] = make_float2(a0, a1);
}

// -------------------------------------------------------------------------
// Kernel 3: persistent fused GRU recurrence + projection + NLL
//   EXACT round-4 structure (418us measured); only activations swapped
//   for MUFU-based fast versions (validated: rel_err 2.5e-7).
// -------------------------------------------------------------------------
__global__ __launch_bounds__(256, 2)
void gru_kernel(const float* __restrict__ Wrh,
                const float* __restrict__ Wzh,
                const float* __restrict__ Whh,
                const float* __restrict__ Wproj,
                const float* __restrict__ bproj,
                float* __restrict__ out) {
    extern __shared__ float sm[];
    float* sWa  = sm;            // [64][128]: W_rh | W_zh, k-major
    float* sWh  = sm + 8192;     // [64][64]
    float* sWp  = sm + 12288;    // [64][32]
    float* sTab = sm + 14336;    // [3][32][64]
    float* sH   = sm + 20480;    // [16][64]
    float* sRH  = sm + 21504;    // [16][64]  r*h
    float* sZ   = sm + 22528;    // [16][64]  z
    int*   sCS  = (int*)(sm + 23552); // [16][65]
    float* sRed = sm + 24592;    // [16]

    const int tid = threadIdx.x;
    const int b0 = blockIdx.x * BT;

    // cooperative init
    for (int i = tid; i < 8192; i += 256) {
        int k = i >> 7, j = i & 127;
        sWa[i] = (j < 64) ? Wrh[k * 64 + j] : Wzh[k * 64 + (j - 64)];
    }
    for (int i = tid; i < 4096; i += 256) sWh[i] = Whh[i];
    for (int i = tid; i < 2048; i += 256) sWp[i] = Wproj[i];
    for (int i = tid; i < 6144; i += 256) sTab[i] = g_table[i];
    for (int i = tid; i < BT * T1; i += 256) {
        int r = i / T1, t = i - r * T1;
        sCS[i] = g_cs[(b0 + r) * T1 + t];
    }
    for (int i = tid; i < BT * 64; i += 256) sH[i] = 0.f;

    // thread mappings
    const int rq = tid >> 6;         // 0..3 -> rows 4*rq..4*rq+3  (pass A/B)
    const int cg = tid & 63;         // 0..63
    const int j0 = cg << 1;          // 0..126 (pass A col pair over [r|z])
    const int gA = (j0 >= 64) ? 1 : 0;
    const int jjA = j0 & 63;
    const int v  = tid & 31;         // pass C vocab col
    const int rg = tid >> 5;         // 0..7 -> rows 2*rg, 2*rg+1 (pass C)

    float pbA[4][2], pbB[4];
#pragma unroll
    for (int r = 0; r < 4; r++) {
        int base = gA * (BB * 64) + (b0 + 4 * rq + r) * 64 + jjA;
        pbA[r][0] = g_phonb[base];
        pbA[r][1] = g_phonb[base + 1];
        pbB[r] = g_phonb[2 * (BB * 64) + (b0 + 4 * rq + r) * 64 + cg];
    }
    const float bp = bproj[v];
    float nllAcc = 0.f, cntAcc = 0.f;

    __syncthreads();

    for (int t = 0; t < TT; t++) {
        // ---------------- Pass A: r,z gates:  h @ [W_rh|W_zh] -------------
        float acc[4][2];
#pragma unroll
        for (int r = 0; r < 4; r++) { acc[r][0] = 0.f; acc[r][1] = 0.f; }
#pragma unroll
        for (int k4 = 0; k4 < 64; k4 += 4) {
            float hr[4][4];
#pragma unroll
            for (int r = 0; r < 4; r++) {
                float4 hv = *(const float4*)&sH[(4 * rq + r) * 64 + k4];
                hr[r][0] = hv.x; hr[r][1] = hv.y; hr[r][2] = hv.z; hr[r][3] = hv.w;
            }
#pragma unroll
            for (int kk = 0; kk < 4; kk++) {
                float2 w = *(const float2*)&sWa[(k4 + kk) * 128 + j0];
#pragma unroll
                for (int r = 0; r < 4; r++) {
                    acc[r][0] = fmaf(hr[r][kk], w.x, acc[r][0]);
                    acc[r][1] = fmaf(hr[r][kk], w.y, acc[r][1]);
                }
            }
        }
        int cc[4];
#pragma unroll
        for (int r = 0; r < 4; r++) cc[r] = sCS[(4 * rq + r) * T1 + t];
        const float* tg_ = sTab + gA * 2048;
#pragma unroll
        for (int r = 0; r < 4; r++) {
            float2 tv = *(const float2*)&tg_[cc[r] * 64 + jjA];
            float p0 = acc[r][0] + tv.x + pbA[r][0];
            float p1 = acc[r][1] + tv.y + pbA[r][1];
            float g0 = sigf(p0);
            float g1 = sigf(p1);
            if (gA == 0) {
                float2 ho = *(const float2*)&sH[(4 * rq + r) * 64 + j0];
                float2 o; o.x = g0 * ho.x; o.y = g1 * ho.y;
                *(float2*)&sRH[(4 * rq + r) * 64 + j0] = o;
            } else {
                float2 o; o.x = g0; o.y = g1;
                *(float2*)&sZ[(4 * rq + r) * 64 + jjA] = o;
            }
        }
        __syncthreads();

        // ---------------- Pass B: candidate:  (r*h) @ W_hh ----------------
        float accB[4] = {0.f, 0.f, 0.f, 0.f};
#pragma unroll
        for (int k4 = 0; k4 < 64; k4 += 4) {
            float rr[4][4];
#pragma unroll
            for (int r = 0; r < 4; r++) {
                float4 rv = *(const float4*)&sRH[(4 * rq + r) * 64 + k4];
                rr[r][0] = rv.x; rr[r][1] = rv.y; rr[r][2] = rv.z; rr[r][3] = rv.w;
            }
#pragma unroll
            for (int kk = 0; kk < 4; kk++) {
                float w = sWh[(k4 + kk) * 64 + cg];
#pragma unroll
                for (int r = 0; r < 4; r++)
                    accB[r] = fmaf(rr[r][kk], w, accB[r]);
            }
        }
#pragma unroll
        for (int r = 0; r < 4; r++) {
            float pre = accB[r] + sTab[4096 + cc[r] * 64 + cg] + pbB[r];
            float cv = tanhfast(pre);
            int hi = (4 * rq + r) * 64 + cg;
            float z = sZ[hi];
            float ho = sH[hi];
            sH[hi] = fmaf(z, cv - ho, ho);   // (1-z)h + z c
        }
        __syncthreads();

        // ---------------- Pass C: logits + log-softmax NLL ----------------
        float accC[2] = {0.f, 0.f};
#pragma unroll
        for (int k4 = 0; k4 < 64; k4 += 4) {
            float h0[4], h1[4];
            float4 a = *(const float4*)&sH[(2 * rg) * 64 + k4];
            float4 b = *(const float4*)&sH[(2 * rg + 1) * 64 + k4];
            h0[0] = a.x; h0[1] = a.y; h0[2] = a.z; h0[3] = a.w;
            h1[0] = b.x; h1[1] = b.y; h1[2] = b.z; h1[3] = b.w;
#pragma unroll
            for (int kk = 0; kk < 4; kk++) {
                float w = sWp[(k4 + kk) * 32 + v];
                accC[0] = fmaf(h0[kk], w, accC[0]);
                accC[1] = fmaf(h1[kk], w, accC[1]);
            }
        }
#pragma unroll
        for (int r = 0; r < 2; r++) {
            int row = 2 * rg + r;
            float lg = accC[r] + bp;
            out[((long long)(b0 + row) * TT + t) * VV + v] = lg;
            int tgt = sCS[row * T1 + t + 1];
            float m = lg;
#pragma unroll
            for (int o = 16; o > 0; o >>= 1)
                m = fmaxf(m, __shfl_xor_sync(0xffffffffu, m, o));
            float s = __expf(lg - m);
#pragma unroll
            for (int o = 16; o > 0; o >>= 1)
                s += __shfl_xor_sync(0xffffffffu, s, o);
            float lt = __shfl_sync(0xffffffffu, lg, tgt);
            if (v == 0 && tgt != 0) {
                nllAcc += m + __logf(s) - lt;
                cntAcc += 1.f;
            }
        }
        // no sync needed: next pass A only reads sH (stable since pass-B sync)
    }

    // deterministic per-block loss partials
    if (v == 0) { sRed[rg] = nllAcc; sRed[8 + rg] = cntAcc; }
    __syncthreads();
    if (tid == 0) {
        float a = 0.f, c = 0.f;
#pragma unroll
        for (int i = 0; i < 8; i++) { a += sRed[i]; c += sRed[8 + i]; }
        g_part[blockIdx.x] = a;
        g_part[NBLK + blockIdx.x] = c;
    }
}

// -------------------------------------------------------------------------
// Kernel 4: final loss reduction (deterministic tree)
// -------------------------------------------------------------------------
__global__ void loss_kernel(float* __restrict__ out, long long out_size) {
    __shared__ float sa[NBLK], sc[NBLK];
    int tid = threadIdx.x;
    sa[tid] = g_part[tid];
    sc[tid] = g_part[NBLK + tid];
    __syncthreads();
    for (int s = NBLK / 2; s > 0; s >>= 1) {
        if (tid < s) { sa[tid] += sa[tid + s]; sc[tid] += sc[tid + s]; }
        __syncthreads();
    }
    if (tid == 0 && out_size > (long long)BB * TT * VV)
        out[out_size - 1] = sa[0] / fmaxf(sc[0], 1.f);
}

// -------------------------------------------------------------------------
extern "C" void kernel_launch(void* const* d_in, const int* in_sizes, int n_in,
                              void* d_out, int out_size) {
    const float* phon  = (const float*)d_in[0];
    const void*  cs    = d_in[1];
    const float* emb   = (const float*)d_in[2];
    const float* Wrx   = (const float*)d_in[3];
    const float* brx   = (const float*)d_in[4];
    const float* Wrh   = (const float*)d_in[5];
    const float* brh   = (const float*)d_in[6];
    const float* Wzx   = (const float*)d_in[7];
    const float* bzx   = (const float*)d_in[8];
    const float* Wzh   = (const float*)d_in[9];
    const float* bzh   = (const float*)d_in[10];
    const float* Whx   = (const float*)d_in[11];
    const float* bhx   = (const float*)d_in[12];
    const float* Whh   = (const float*)d_in[13];
    const float* bhh   = (const float*)d_in[14];
    const float* Wproj = (const float*)d_in[15];
    const float* bproj = (const float*)d_in[16];
    float* out = (float*)d_out;

    (void)cudaFuncSetAttribute(gru_kernel,
                               cudaFuncAttributeMaxDynamicSharedMemorySize,
                               SMEM_BYTES);

    detect_kernel<<<1, 1024>>>((const int*)cs, BB * T1);
    convert_kernel<<<(BB * T1 + 255) / 256, 256>>>(cs);
    table_kernel<<<24, 256>>>(emb, Wrx, Wzx, Whx);
    phonb_kernel<<<(3 * BB * 32 + 255) / 256, 256>>>(phon, Wrx, Wzx, Whx,
                                                     brx, brh, bzx, bzh, bhx, bhh);
    gru_kernel<<<NBLK, 256, SMEM_BYTES>>>(Wrh, Wzh, Whh, Wproj, bproj, out);
    loss_kernel<<<1, 256>>>(out, (long long)out_size);
}

// round 10
// speedup vs baseline: 2.5263x; 1.0103x over previous
#include <cuda_runtime.h>

#define BB 4096
#define TT 64
#define T1 65
#define HH 64
#define PP 50
#define VV 32
#define BT 16
#define NBLK (BB / BT) /* 256 */

#define SMEM_FLOATS 24608
#define SMEM_BYTES (SMEM_FLOATS * 4)

// scratch (device globals; no allocation allowed)
__device__ float g_table[3 * 32 * 64];
__device__ float g_phonb[3 * BB * 64];
__device__ float g_part[2 * NBLK];
__device__ int   g_cs[BB * T1];
__device__ int   g_flag;

// ---- helpers --------------------------------------------------------------
__device__ __forceinline__ unsigned long long fma2(unsigned long long a,
                                                   unsigned long long b,
                                                   unsigned long long c) {
    asm("fma.rn.f32x2 %0, %1, %2, %0;" : "+l"(c) : "l"(a), "l"(b));
    return c;
}
__device__ __forceinline__ unsigned long long pack2(float a, float b) {
    unsigned long long d;
    asm("mov.b64 %0, {%1, %2};" : "=l"(d)
        : "r"(__float_as_uint(a)), "r"(__float_as_uint(b)));
    return d;
}
__device__ __forceinline__ unsigned long long dup2(float v) {
    unsigned long long d;
    unsigned int u = __float_as_uint(v);
    asm("mov.b64 %0, {%1, %1};" : "=l"(d) : "r"(u));
    return d;
}
__device__ __forceinline__ void unpack2(unsigned long long d, float& a, float& b) {
    unsigned int x, y;
    asm("mov.b64 {%0, %1}, %2;" : "=r"(x), "=r"(y) : "l"(d));
    a = __uint_as_float(x);
    b = __uint_as_float(y);
}
__device__ __forceinline__ float sigf(float x) {
    float e = __expf(-x);
    return __fdividef(1.f, 1.f + e);
}
__device__ __forceinline__ float tanhfast(float x) {
    float e = __expf(-2.f * x);
    return __fdividef(2.f, 1.f + e) - 1.f;
}

// -------------------------------------------------------------------------
// Kernel 0a: detect char_seq dtype (odd-word OR; 0 <=> int64 storage)
// -------------------------------------------------------------------------
__global__ void detect_kernel(const int* __restrict__ src, int nelem) {
    __shared__ int sh[1024];
    int acc = 0;
    for (int i = threadIdx.x; i < nelem; i += 1024)
        if (i & 1) acc |= src[i];
    sh[threadIdx.x] = acc;
    __syncthreads();
    for (int s = 512; s > 0; s >>= 1) {
        if (threadIdx.x < s) sh[threadIdx.x] |= sh[threadIdx.x + s];
        __syncthreads();
    }
    if (threadIdx.x == 0) g_flag = sh[0];
}

__global__ void convert_kernel(const void* __restrict__ src) {
    int i = blockIdx.x * blockDim.x + threadIdx.x;
    if (i >= BB * T1) return;
    if (g_flag != 0) g_cs[i] = ((const int*)src)[i];
    else             g_cs[i] = (int)((const long long*)src)[i];
}

// -------------------------------------------------------------------------
// Kernel 1: char table  table[g][c][j] = sum_k emb[c][k] * W_gx[k][j]
// -------------------------------------------------------------------------
__global__ void table_kernel(const float* __restrict__ emb,
                             const float* __restrict__ Wrx,
                             const float* __restrict__ Wzx,
                             const float* __restrict__ Whx) {
    int idx = blockIdx.x * blockDim.x + threadIdx.x;
    if (idx >= 3 * 32 * 64) return;
    int g = idx >> 11;
    int rem = idx & 2047;
    int c = rem >> 6;
    int j = rem & 63;
    const float* W = (g == 0) ? Wrx : ((g == 1) ? Wzx : Whx);
    const float* e = emb + c * HH;
    float acc = 0.f;
#pragma unroll
    for (int k = 0; k < HH; k++) acc = fmaf(e[k], W[k * HH + j], acc);
    g_table[idx] = acc;
}

// -------------------------------------------------------------------------
// Kernel 2: phon part (f32x2 over j-pairs)
// -------------------------------------------------------------------------
__global__ void phonb_kernel(const float* __restrict__ phon,
                             const float* __restrict__ Wrx,
                             const float* __restrict__ Wzx,
                             const float* __restrict__ Whx,
                             const float* __restrict__ brx,
                             const float* __restrict__ brh,
                             const float* __restrict__ bzx,
                             const float* __restrict__ bzh,
                             const float* __restrict__ bhx,
                             const float* __restrict__ bhh) {
    int idx = blockIdx.x * blockDim.x + threadIdx.x;
    if (idx >= 3 * BB * 32) return;
    int g = idx / (BB * 32);
    int rem = idx - g * (BB * 32);
    int b = rem >> 5;
    int jp = rem & 31;
    const float* W  = (g == 0) ? Wrx : ((g == 1) ? Wzx : Whx);
    const float* bx = (g == 0) ? brx : ((g == 1) ? bzx : bhx);
    const float* bh = (g == 0) ? brh : ((g == 1) ? bzh : bhh);
    float2 x2 = *(const float2*)&bx[jp * 2];
    float2 h2 = *(const float2*)&bh[jp * 2];
    unsigned long long acc = pack2(x2.x + h2.x, x2.y + h2.y);
    const float* ph = phon + b * PP;
#pragma unroll
    for (int p = 0; p < PP; p++) {
        unsigned long long d = dup2(ph[p]);
        unsigned long long w = *(const unsigned long long*)&W[(HH + p) * HH + jp * 2];
        acc = fma2(d, w, acc);
    }
    float a0, a1;
    unpack2(acc, a0, a1);
    *(float2*)&g_phonb[g * (BB * 64) + b * 64 + jp * 2] = make_float2(a0, a1);
}

// -------------------------------------------------------------------------
// Kernel 3: persistent fused GRU recurrence + projection + NLL
//   Round-9 structure, but h / r*h / z stored ROW-PAIR interleaved:
//     sXp[pair][k][2] with [0]=row 2p, [1]=row 2p+1
//   so float4 broadcasts yield aligned 64-bit (r0,r1) operands for
//   fma.rn.f32x2 — halves fma-pipe issue, identical LDS pattern.
// -------------------------------------------------------------------------
__global__ __launch_bounds__(256, 2)
void gru_kernel(const float* __restrict__ Wrh,
                const float* __restrict__ Wzh,
                const float* __restrict__ Whh,
                const float* __restrict__ Wproj,
                const float* __restrict__ bproj,
                float* __restrict__ out) {
    extern __shared__ float sm[];
    float* sWa  = sm;            // [64][128]: W_rh | W_zh, k-major
    float* sWh  = sm + 8192;     // [64][64]
    float* sWp  = sm + 12288;    // [64][32]
    float* sTab = sm + 14336;    // [3][32][64]
    float* sHp  = sm + 20480;    // [8 pairs][64 k][2]
    float* sRHp = sm + 21504;    // [8][64][2]  r*h
    float* sZp  = sm + 22528;    // [8][64][2]  z
    int*   sCS  = (int*)(sm + 23552); // [16][65]
    float* sRed = sm + 24592;    // [16]

    const int tid = threadIdx.x;
    const int b0 = blockIdx.x * BT;

    // cooperative init
    for (int i = tid; i < 8192; i += 256) {
        int k = i >> 7, j = i & 127;
        sWa[i] = (j < 64) ? Wrh[k * 64 + j] : Wzh[k * 64 + (j - 64)];
    }
    for (int i = tid; i < 4096; i += 256) sWh[i] = Whh[i];
    for (int i = tid; i < 2048; i += 256) sWp[i] = Wproj[i];
    for (int i = tid; i < 6144; i += 256) sTab[i] = g_table[i];
    for (int i = tid; i < BT * T1; i += 256) {
        int r = i / T1, t = i - r * T1;
        sCS[i] = g_cs[(b0 + r) * T1 + t];
    }
    for (int i = tid; i < BT * 64; i += 256) sHp[i] = 0.f;

    // thread mappings
    const int rq = tid >> 6;         // 0..3 -> rows 4*rq..4*rq+3 (pairs 2rq, 2rq+1)
    const int cg = tid & 63;         // 0..63
    const int j0 = cg << 1;          // 0..126 (pass A col pair over [r|z])
    const int gA = (j0 >= 64) ? 1 : 0;
    const int jjA = j0 & 63;
    const int v  = tid & 31;         // pass C vocab col
    const int rg = tid >> 5;         // 0..7 -> pair rg (rows 2rg, 2rg+1)

    const int pA0 = 2 * rq, pA1 = 2 * rq + 1;
    const float* hp0 = sHp + pA0 * 128;
    const float* hp1 = sHp + pA1 * 128;
    const float* rp0 = sRHp + pA0 * 128;
    const float* rp1 = sRHp + pA1 * 128;

    float pbA[4][2], pbB[4];
#pragma unroll
    for (int r = 0; r < 4; r++) {
        int base = gA * (BB * 64) + (b0 + 4 * rq + r) * 64 + jjA;
        pbA[r][0] = g_phonb[base];
        pbA[r][1] = g_phonb[base + 1];
        pbB[r] = g_phonb[2 * (BB * 64) + (b0 + 4 * rq + r) * 64 + cg];
    }
    const float bp = bproj[v];
    float nllAcc = 0.f, cntAcc = 0.f;

    __syncthreads();

    for (int t = 0; t < TT; t++) {
        int cc[4];
#pragma unroll
        for (int r = 0; r < 4; r++) cc[r] = sCS[(4 * rq + r) * T1 + t];

        // ---------------- Pass A: r,z gates:  h @ [W_rh|W_zh] -------------
        // acc[pair][col] packed over rows of the pair
        unsigned long long aP0c0 = 0, aP0c1 = 0, aP1c0 = 0, aP1c1 = 0;
#pragma unroll
        for (int k4 = 0; k4 < 64; k4 += 4) {
            float4 A0 = *(const float4*)(hp0 + 2 * k4);       // k4, k4+1
            float4 A1 = *(const float4*)(hp0 + 2 * k4 + 4);   // k4+2, k4+3
            float4 B0 = *(const float4*)(hp1 + 2 * k4);
            float4 B1 = *(const float4*)(hp1 + 2 * k4 + 4);
            unsigned long long h0[4], h1[4];
            h0[0] = pack2(A0.x, A0.y); h0[1] = pack2(A0.z, A0.w);
            h0[2] = pack2(A1.x, A1.y); h0[3] = pack2(A1.z, A1.w);
            h1[0] = pack2(B0.x, B0.y); h1[1] = pack2(B0.z, B0.w);
            h1[2] = pack2(B1.x, B1.y); h1[3] = pack2(B1.z, B1.w);
#pragma unroll
            for (int kk = 0; kk < 4; kk++) {
                float2 w = *(const float2*)&sWa[(k4 + kk) * 128 + j0];
                unsigned long long wx = dup2(w.x);
                unsigned long long wy = dup2(w.y);
                aP0c0 = fma2(h0[kk], wx, aP0c0);
                aP0c1 = fma2(h0[kk], wy, aP0c1);
                aP1c0 = fma2(h1[kk], wx, aP1c0);
                aP1c1 = fma2(h1[kk], wy, aP1c1);
            }
        }
        {
            float a00, a10, a01, a11, a20, a30, a21, a31;
            unpack2(aP0c0, a00, a10);   // rows 4rq, 4rq+1 @ col jjA
            unpack2(aP0c1, a01, a11);   // @ col jjA+1
            unpack2(aP1c0, a20, a30);   // rows 4rq+2, 4rq+3 @ col jjA
            unpack2(aP1c1, a21, a31);
            const float* tg_ = sTab + gA * 2048;
            float2 t0 = *(const float2*)&tg_[cc[0] * 64 + jjA];
            float2 t1 = *(const float2*)&tg_[cc[1] * 64 + jjA];
            float2 t2 = *(const float2*)&tg_[cc[2] * 64 + jjA];
            float2 t3 = *(const float2*)&tg_[cc[3] * 64 + jjA];
            float g00 = sigf(a00 + t0.x + pbA[0][0]);
            float g01 = sigf(a01 + t0.y + pbA[0][1]);
            float g10 = sigf(a10 + t1.x + pbA[1][0]);
            float g11 = sigf(a11 + t1.y + pbA[1][1]);
            float g20 = sigf(a20 + t2.x + pbA[2][0]);
            float g21 = sigf(a21 + t2.y + pbA[2][1]);
            float g30 = sigf(a30 + t3.x + pbA[3][0]);
            float g31 = sigf(a31 + t3.y + pbA[3][1]);
            if (gA == 0) {
                float4 H0 = *(const float4*)(hp0 + 2 * jjA); // (h[r0][c0],h[r1][c0],h[r0][c1],h[r1][c1])
                float4 H1 = *(const float4*)(hp1 + 2 * jjA);
                *(float4*)(sRHp + pA0 * 128 + 2 * jjA) =
                    make_float4(g00 * H0.x, g10 * H0.y, g01 * H0.z, g11 * H0.w);
                *(float4*)(sRHp + pA1 * 128 + 2 * jjA) =
                    make_float4(g20 * H1.x, g30 * H1.y, g21 * H1.z, g31 * H1.w);
            } else {
                *(float4*)(sZp + pA0 * 128 + 2 * jjA) = make_float4(g00, g10, g01, g11);
                *(float4*)(sZp + pA1 * 128 + 2 * jjA) = make_float4(g20, g30, g21, g31);
            }
        }
        __syncthreads();

        // ---------------- Pass B: candidate:  (r*h) @ W_hh ----------------
        unsigned long long bP0 = 0, bP1 = 0;
#pragma unroll
        for (int k4 = 0; k4 < 64; k4 += 4) {
            float4 R0 = *(const float4*)(rp0 + 2 * k4);
            float4 R1 = *(const float4*)(rp0 + 2 * k4 + 4);
            float4 S0 = *(const float4*)(rp1 + 2 * k4);
            float4 S1 = *(const float4*)(rp1 + 2 * k4 + 4);
            unsigned long long r0[4], r1[4];
            r0[0] = pack2(R0.x, R0.y); r0[1] = pack2(R0.z, R0.w);
            r0[2] = pack2(R1.x, R1.y); r0[3] = pack2(R1.z, R1.w);
            r1[0] = pack2(S0.x, S0.y); r1[1] = pack2(S0.z, S0.w);
            r1[2] = pack2(S1.x, S1.y); r1[3] = pack2(S1.z, S1.w);
#pragma unroll
            for (int kk = 0; kk < 4; kk++) {
                unsigned long long wd = dup2(sWh[(k4 + kk) * 64 + cg]);
                bP0 = fma2(r0[kk], wd, bP0);
                bP1 = fma2(r1[kk], wd, bP1);
            }
        }
        {
            float x0, x1, x2, x3;
            unpack2(bP0, x0, x1);   // rows 4rq, 4rq+1 @ col cg
            unpack2(bP1, x2, x3);
            float cv0 = tanhfast(x0 + sTab[4096 + cc[0] * 64 + cg] + pbB[0]);
            float cv1 = tanhfast(x1 + sTab[4096 + cc[1] * 64 + cg] + pbB[1]);
            float cv2 = tanhfast(x2 + sTab[4096 + cc[2] * 64 + cg] + pbB[2]);
            float cv3 = tanhfast(x3 + sTab[4096 + cc[3] * 64 + cg] + pbB[3]);
            float2 Z0 = *(const float2*)(sZp + pA0 * 128 + 2 * cg);
            float2 Z1 = *(const float2*)(sZp + pA1 * 128 + 2 * cg);
            float2 Hh0 = *(const float2*)(hp0 + 2 * cg);
            float2 Hh1 = *(const float2*)(hp1 + 2 * cg);
            float hn0 = fmaf(Z0.x, cv0 - Hh0.x, Hh0.x);
            float hn1 = fmaf(Z0.y, cv1 - Hh0.y, Hh0.y);
            float hn2 = fmaf(Z1.x, cv2 - Hh1.x, Hh1.x);
            float hn3 = fmaf(Z1.y, cv3 - Hh1.y, Hh1.y);
            *(float2*)(sHp + pA0 * 128 + 2 * cg) = make_float2(hn0, hn1);
            *(float2*)(sHp + pA1 * 128 + 2 * cg) = make_float2(hn2, hn3);
        }
        __syncthreads();

        // ---------------- Pass C: logits + log-softmax NLL ----------------
        unsigned long long cP = 0;
        const float* hc = sHp + rg * 128;
#pragma unroll
        for (int k4 = 0; k4 < 64; k4 += 4) {
            float4 A = *(const float4*)(hc + 2 * k4);
            float4 B = *(const float4*)(hc + 2 * k4 + 4);
            unsigned long long hp[4];
            hp[0] = pack2(A.x, A.y); hp[1] = pack2(A.z, A.w);
            hp[2] = pack2(B.x, B.y); hp[3] = pack2(B.z, B.w);
#pragma unroll
            for (int kk = 0; kk < 4; kk++) {
                unsigned long long wd = dup2(sWp[(k4 + kk) * 32 + v]);
                cP = fma2(hp[kk], wd, cP);
            }
        }
        float accC[2];
        unpack2(cP, accC[0], accC[1]);   // rows 2rg, 2rg+1
#pragma unroll
        for (int r = 0; r < 2; r++) {
            int row = 2 * rg + r;
            float lg = accC[r] + bp;
            out[((long long)(b0 + row) * TT + t) * VV + v] = lg;
            int tgt = sCS[row * T1 + t + 1];
            float m = lg;
#pragma unroll
            for (int o = 16; o > 0; o >>= 1)
                m = fmaxf(m, __shfl_xor_sync(0xffffffffu, m, o));
            float s = __expf(lg - m);
#pragma unroll
            for (int o = 16; o > 0; o >>= 1)
                s += __shfl_xor_sync(0xffffffffu, s, o);
            float lt = __shfl_sync(0xffffffffu, lg, tgt);
            if (v == 0 && tgt != 0) {
                nllAcc += m + __logf(s) - lt;
                cntAcc += 1.f;
            }
        }
        // no sync needed: next pass A only reads sHp (stable since pass-B sync)
    }

    // deterministic per-block loss partials
    if (v == 0) { sRed[rg] = nllAcc; sRed[8 + rg] = cntAcc; }
    __syncthreads();
    if (tid == 0) {
        float a = 0.f, c = 0.f;
#pragma unroll
        for (int i = 0; i < 8; i++) { a += sRed[i]; c += sRed[8 + i]; }
        g_part[blockIdx.x] = a;
        g_part[NBLK + blockIdx.x] = c;
    }
}

// -------------------------------------------------------------------------
// Kernel 4: final loss reduction (deterministic tree)
// -------------------------------------------------------------------------
__global__ void loss_kernel(float* __restrict__ out, long long out_size) {
    __shared__ float sa[NBLK], sc[NBLK];
    int tid = threadIdx.x;
    sa[tid] = g_part[tid];
    sc[tid] = g_part[NBLK + tid];
    __syncthreads();
    for (int s = NBLK / 2; s > 0; s >>= 1) {
        if (tid < s) { sa[tid] += sa[tid + s]; sc[tid] += sc[tid + s]; }
        __syncthreads();
    }
    if (tid == 0 && out_size > (long long)BB * TT * VV)
        out[out_size - 1] = sa[0] / fmaxf(sc[0], 1.f);
}

// -------------------------------------------------------------------------
extern "C" void kernel_launch(void* const* d_in, const int* in_sizes, int n_in,
                              void* d_out, int out_size) {
    const float* phon  = (const float*)d_in[0];
    const void*  cs    = d_in[1];
    const float* emb   = (const float*)d_in[2];
    const float* Wrx   = (const float*)d_in[3];
    const float* brx   = (const float*)d_in[4];
    const float* Wrh   = (const float*)d_in[5];
    const float* brh   = (const float*)d_in[6];
    const float* Wzx   = (const float*)d_in[7];
    const float* bzx   = (const float*)d_in[8];
    const float* Wzh   = (const float*)d_in[9];
    const float* bzh   = (const float*)d_in[10];
    const float* Whx   = (const float*)d_in[11];
    const float* bhx   = (const float*)d_in[12];
    const float* Whh   = (const float*)d_in[13];
    const float* bhh   = (const float*)d_in[14];
    const float* Wproj = (const float*)d_in[15];
    const float* bproj = (const float*)d_in[16];
    float* out = (float*)d_out;

    (void)cudaFuncSetAttribute(gru_kernel,
                               cudaFuncAttributeMaxDynamicSharedMemorySize,
                               SMEM_BYTES);

    detect_kernel<<<1, 1024>>>((const int*)cs, BB * T1);
    convert_kernel<<<(BB * T1 + 255) / 256, 256>>>(cs);
    table_kernel<<<24, 256>>>(emb, Wrx, Wzx, Whx);
    phonb_kernel<<<(3 * BB * 32 + 255) / 256, 256>>>(phon, Wrx, Wzx, Whx,
                                                     brx, brh, bzx, bzh, bhx, bhh);
    gru_kernel<<<NBLK, 256, SMEM_BYTES>>>(Wrh, Wzh, Whh, Wproj, bproj, out);
    loss_kernel<<<1, 256>>>(out, (long long)out_size);
}

// round 11
// speedup vs baseline: 2.6229x; 1.0382x over previous
#include <cuda_runtime.h>

#define BB 4096
#define TT 64
#define T1 65
#define HH 64
#define PP 50
#define VV 32
#define BT 16
#define NBLK (BB / BT) /* 256 */

#define SMEM_FLOATS 24608
#define SMEM_BYTES (SMEM_FLOATS * 4)

// scratch (device globals; no allocation allowed)
__device__ float g_table[3 * 32 * 64];
__device__ float g_phonb[3 * BB * 64];
__device__ float g_part[2 * NBLK];
__device__ int   g_cs[BB * T1];
__device__ int   g_flag;

// ---- helpers --------------------------------------------------------------
__device__ __forceinline__ unsigned long long fma2(unsigned long long a,
                                                   unsigned long long b,
                                                   unsigned long long c) {
    asm("fma.rn.f32x2 %0, %1, %2, %0;" : "+l"(c) : "l"(a), "l"(b));
    return c;
}
__device__ __forceinline__ unsigned long long pack2(float a, float b) {
    unsigned long long d;
    asm("mov.b64 %0, {%1, %2};" : "=l"(d)
        : "r"(__float_as_uint(a)), "r"(__float_as_uint(b)));
    return d;
}
__device__ __forceinline__ unsigned long long dup2(float v) {
    unsigned long long d;
    unsigned int u = __float_as_uint(v);
    asm("mov.b64 %0, {%1, %1};" : "=l"(d) : "r"(u));
    return d;
}
__device__ __forceinline__ void unpack2(unsigned long long d, float& a, float& b) {
    unsigned int x, y;
    asm("mov.b64 {%0, %1}, %2;" : "=r"(x), "=r"(y) : "l"(d));
    a = __uint_as_float(x);
    b = __uint_as_float(y);
}
__device__ __forceinline__ float sigf(float x) {
    float e = __expf(-x);
    return __fdividef(1.f, 1.f + e);
}
__device__ __forceinline__ float tanhfast(float x) {
    float e = __expf(-2.f * x);
    return __fdividef(2.f, 1.f + e) - 1.f;
}
// pair-scoped barrier: warps {2m, 2m+1} (64 threads), ids 1..4
__device__ __forceinline__ void pair_bar(int m) {
    asm volatile("bar.sync %0, 64;" :: "r"(m + 1) : "memory");
}

// -------------------------------------------------------------------------
// Kernel 0a: detect char_seq dtype (odd-word OR; 0 <=> int64 storage)
// -------------------------------------------------------------------------
__global__ void detect_kernel(const int* __restrict__ src, int nelem) {
    __shared__ int sh[1024];
    int acc = 0;
    for (int i = threadIdx.x; i < nelem; i += 1024)
        if (i & 1) acc |= src[i];
    sh[threadIdx.x] = acc;
    __syncthreads();
    for (int s = 512; s > 0; s >>= 1) {
        if (threadIdx.x < s) sh[threadIdx.x] |= sh[threadIdx.x + s];
        __syncthreads();
    }
    if (threadIdx.x == 0) g_flag = sh[0];
}

__global__ void convert_kernel(const void* __restrict__ src) {
    int i = blockIdx.x * blockDim.x + threadIdx.x;
    if (i >= BB * T1) return;
    if (g_flag != 0) g_cs[i] = ((const int*)src)[i];
    else             g_cs[i] = (int)((const long long*)src)[i];
}

// -------------------------------------------------------------------------
// Kernel 1: char table  table[g][c][j] = sum_k emb[c][k] * W_gx[k][j]
// -------------------------------------------------------------------------
__global__ void table_kernel(const float* __restrict__ emb,
                             const float* __restrict__ Wrx,
                             const float* __restrict__ Wzx,
                             const float* __restrict__ Whx) {
    int idx = blockIdx.x * blockDim.x + threadIdx.x;
    if (idx >= 3 * 32 * 64) return;
    int g = idx >> 11;
    int rem = idx & 2047;
    int c = rem >> 6;
    int j = rem & 63;
    const float* W = (g == 0) ? Wrx : ((g == 1) ? Wzx : Whx);
    const float* e = emb + c * HH;
    float acc = 0.f;
#pragma unroll
    for (int k = 0; k < HH; k++) acc = fmaf(e[k], W[k * HH + j], acc);
    g_table[idx] = acc;
}

// -------------------------------------------------------------------------
// Kernel 2: phon part (f32x2 over j-pairs)
// -------------------------------------------------------------------------
__global__ void phonb_kernel(const float* __restrict__ phon,
                             const float* __restrict__ Wrx,
                             const float* __restrict__ Wzx,
                             const float* __restrict__ Whx,
                             const float* __restrict__ brx,
                             const float* __restrict__ brh,
                             const float* __restrict__ bzx,
                             const float* __restrict__ bzh,
                             const float* __restrict__ bhx,
                             const float* __restrict__ bhh) {
    int idx = blockIdx.x * blockDim.x + threadIdx.x;
    if (idx >= 3 * BB * 32) return;
    int g = idx / (BB * 32);
    int rem = idx - g * (BB * 32);
    int b = rem >> 5;
    int jp = rem & 31;
    const float* W  = (g == 0) ? Wrx : ((g == 1) ? Wzx : Whx);
    const float* bx = (g == 0) ? brx : ((g == 1) ? bzx : bhx);
    const float* bh = (g == 0) ? brh : ((g == 1) ? bzh : bhh);
    float2 x2 = *(const float2*)&bx[jp * 2];
    float2 h2 = *(const float2*)&bh[jp * 2];
    unsigned long long acc = pack2(x2.x + h2.x, x2.y + h2.y);
    const float* ph = phon + b * PP;
#pragma unroll
    for (int p = 0; p < PP; p++) {
        unsigned long long d = dup2(ph[p]);
        unsigned long long w = *(const unsigned long long*)&W[(HH + p) * HH + jp * 2];
        acc = fma2(d, w, acc);
    }
    float a0, a1;
    unpack2(acc, a0, a1);
    *(float2*)&g_phonb[g * (BB * 64) + b * 64 + jp * 2] = make_float2(a0, a1);
}

// -------------------------------------------------------------------------
// Kernel 3: persistent fused GRU recurrence + projection + NLL
//   Row-pair f32x2 structure (387.5us) with PAIR-SCOPED named barriers:
//   all inter-pass smem dependencies are confined to warp pairs {2m,2m+1},
//   so bar.sync(m+1, 64) replaces block-wide __syncthreads() in the loop.
// -------------------------------------------------------------------------
__global__ __launch_bounds__(256, 2)
void gru_kernel(const float* __restrict__ Wrh,
                const float* __restrict__ Wzh,
                const float* __restrict__ Whh,
                const float* __restrict__ Wproj,
                const float* __restrict__ bproj,
                float* __restrict__ out) {
    extern __shared__ float sm[];
    float* sWa  = sm;            // [64][128]: W_rh | W_zh, k-major
    float* sWh  = sm + 8192;     // [64][64]
    float* sWp  = sm + 12288;    // [64][32]
    float* sTab = sm + 14336;    // [3][32][64]
    float* sHp  = sm + 20480;    // [8 pairs][64 k][2]
    float* sRHp = sm + 21504;    // [8][64][2]  r*h
    float* sZp  = sm + 22528;    // [8][64][2]  z
    int*   sCS  = (int*)(sm + 23552); // [16][65]
    float* sRed = sm + 24592;    // [16]

    const int tid = threadIdx.x;
    const int b0 = blockIdx.x * BT;

    // cooperative init
    for (int i = tid; i < 8192; i += 256) {
        int k = i >> 7, j = i & 127;
        sWa[i] = (j < 64) ? Wrh[k * 64 + j] : Wzh[k * 64 + (j - 64)];
    }
    for (int i = tid; i < 4096; i += 256) sWh[i] = Whh[i];
    for (int i = tid; i < 2048; i += 256) sWp[i] = Wproj[i];
    for (int i = tid; i < 6144; i += 256) sTab[i] = g_table[i];
    for (int i = tid; i < BT * T1; i += 256) {
        int r = i / T1, t = i - r * T1;
        sCS[i] = g_cs[(b0 + r) * T1 + t];
    }
    for (int i = tid; i < BT * 64; i += 256) sHp[i] = 0.f;

    // thread mappings
    const int rq = tid >> 6;         // 0..3 = pair-group id (rows 4rq..4rq+3)
    const int cg = tid & 63;         // 0..63
    const int j0 = cg << 1;          // 0..126 (pass A col pair over [r|z])
    const int gA = (j0 >= 64) ? 1 : 0;
    const int jjA = j0 & 63;
    const int v  = tid & 31;         // pass C vocab col
    const int rg = tid >> 5;         // 0..7 -> pair rg (rows 2rg, 2rg+1)

    const int pA0 = 2 * rq, pA1 = 2 * rq + 1;
    const float* hp0 = sHp + pA0 * 128;
    const float* hp1 = sHp + pA1 * 128;
    const float* rp0 = sRHp + pA0 * 128;
    const float* rp1 = sRHp + pA1 * 128;

    float pbA[4][2], pbB[4];
#pragma unroll
    for (int r = 0; r < 4; r++) {
        int base = gA * (BB * 64) + (b0 + 4 * rq + r) * 64 + jjA;
        pbA[r][0] = g_phonb[base];
        pbA[r][1] = g_phonb[base + 1];
        pbB[r] = g_phonb[2 * (BB * 64) + (b0 + 4 * rq + r) * 64 + cg];
    }
    const float bp = bproj[v];
    float nllAcc = 0.f, cntAcc = 0.f;

    __syncthreads();

    for (int t = 0; t < TT; t++) {
        int cc[4];
#pragma unroll
        for (int r = 0; r < 4; r++) cc[r] = sCS[(4 * rq + r) * T1 + t];

        // ---------------- Pass A: r,z gates:  h @ [W_rh|W_zh] -------------
        unsigned long long aP0c0 = 0, aP0c1 = 0, aP1c0 = 0, aP1c1 = 0;
#pragma unroll
        for (int k4 = 0; k4 < 64; k4 += 4) {
            float4 A0 = *(const float4*)(hp0 + 2 * k4);
            float4 A1 = *(const float4*)(hp0 + 2 * k4 + 4);
            float4 B0 = *(const float4*)(hp1 + 2 * k4);
            float4 B1 = *(const float4*)(hp1 + 2 * k4 + 4);
            unsigned long long h0[4], h1[4];
            h0[0] = pack2(A0.x, A0.y); h0[1] = pack2(A0.z, A0.w);
            h0[2] = pack2(A1.x, A1.y); h0[3] = pack2(A1.z, A1.w);
            h1[0] = pack2(B0.x, B0.y); h1[1] = pack2(B0.z, B0.w);
            h1[2] = pack2(B1.x, B1.y); h1[3] = pack2(B1.z, B1.w);
#pragma unroll
            for (int kk = 0; kk < 4; kk++) {
                float2 w = *(const float2*)&sWa[(k4 + kk) * 128 + j0];
                unsigned long long wx = dup2(w.x);
                unsigned long long wy = dup2(w.y);
                aP0c0 = fma2(h0[kk], wx, aP0c0);
                aP0c1 = fma2(h0[kk], wy, aP0c1);
                aP1c0 = fma2(h1[kk], wx, aP1c0);
                aP1c1 = fma2(h1[kk], wy, aP1c1);
            }
        }
        {
            float a00, a10, a01, a11, a20, a30, a21, a31;
            unpack2(aP0c0, a00, a10);
            unpack2(aP0c1, a01, a11);
            unpack2(aP1c0, a20, a30);
            unpack2(aP1c1, a21, a31);
            const float* tg_ = sTab + gA * 2048;
            float2 t0 = *(const float2*)&tg_[cc[0] * 64 + jjA];
            float2 t1 = *(const float2*)&tg_[cc[1] * 64 + jjA];
            float2 t2 = *(const float2*)&tg_[cc[2] * 64 + jjA];
            float2 t3 = *(const float2*)&tg_[cc[3] * 64 + jjA];
            float g00 = sigf(a00 + t0.x + pbA[0][0]);
            float g01 = sigf(a01 + t0.y + pbA[0][1]);
            float g10 = sigf(a10 + t1.x + pbA[1][0]);
            float g11 = sigf(a11 + t1.y + pbA[1][1]);
            float g20 = sigf(a20 + t2.x + pbA[2][0]);
            float g21 = sigf(a21 + t2.y + pbA[2][1]);
            float g30 = sigf(a30 + t3.x + pbA[3][0]);
            float g31 = sigf(a31 + t3.y + pbA[3][1]);
            if (gA == 0) {
                float4 H0 = *(const float4*)(hp0 + 2 * jjA);
                float4 H1 = *(const float4*)(hp1 + 2 * jjA);
                *(float4*)(sRHp + pA0 * 128 + 2 * jjA) =
                    make_float4(g00 * H0.x, g10 * H0.y, g01 * H0.z, g11 * H0.w);
                *(float4*)(sRHp + pA1 * 128 + 2 * jjA) =
                    make_float4(g20 * H1.x, g30 * H1.y, g21 * H1.z, g31 * H1.w);
            } else {
                *(float4*)(sZp + pA0 * 128 + 2 * jjA) = make_float4(g00, g10, g01, g11);
                *(float4*)(sZp + pA1 * 128 + 2 * jjA) = make_float4(g20, g30, g21, g31);
            }
        }
        pair_bar(rq);

        // ---------------- Pass B: candidate:  (r*h) @ W_hh ----------------
        unsigned long long bP0 = 0, bP1 = 0;
#pragma unroll
        for (int k4 = 0; k4 < 64; k4 += 4) {
            float4 R0 = *(const float4*)(rp0 + 2 * k4);
            float4 R1 = *(const float4*)(rp0 + 2 * k4 + 4);
            float4 S0 = *(const float4*)(rp1 + 2 * k4);
            float4 S1 = *(const float4*)(rp1 + 2 * k4 + 4);
            unsigned long long r0[4], r1[4];
            r0[0] = pack2(R0.x, R0.y); r0[1] = pack2(R0.z, R0.w);
            r0[2] = pack2(R1.x, R1.y); r0[3] = pack2(R1.z, R1.w);
            r1[0] = pack2(S0.x, S0.y); r1[1] = pack2(S0.z, S0.w);
            r1[2] = pack2(S1.x, S1.y); r1[3] = pack2(S1.z, S1.w);
#pragma unroll
            for (int kk = 0; kk < 4; kk++) {
                unsigned long long wd = dup2(sWh[(k4 + kk) * 64 + cg]);
                bP0 = fma2(r0[kk], wd, bP0);
                bP1 = fma2(r1[kk], wd, bP1);
            }
        }
        {
            float x0, x1, x2, x3;
            unpack2(bP0, x0, x1);
            unpack2(bP1, x2, x3);
            float cv0 = tanhfast(x0 + sTab[4096 + cc[0] * 64 + cg] + pbB[0]);
            float cv1 = tanhfast(x1 + sTab[4096 + cc[1] * 64 + cg] + pbB[1]);
            float cv2 = tanhfast(x2 + sTab[4096 + cc[2] * 64 + cg] + pbB[2]);
            float cv3 = tanhfast(x3 + sTab[4096 + cc[3] * 64 + cg] + pbB[3]);
            float2 Z0 = *(const float2*)(sZp + pA0 * 128 + 2 * cg);
            float2 Z1 = *(const float2*)(sZp + pA1 * 128 + 2 * cg);
            float2 Hh0 = *(const float2*)(hp0 + 2 * cg);
            float2 Hh1 = *(const float2*)(hp1 + 2 * cg);
            float hn0 = fmaf(Z0.x, cv0 - Hh0.x, Hh0.x);
            float hn1 = fmaf(Z0.y, cv1 - Hh0.y, Hh0.y);
            float hn2 = fmaf(Z1.x, cv2 - Hh1.x, Hh1.x);
            float hn3 = fmaf(Z1.y, cv3 - Hh1.y, Hh1.y);
            *(float2*)(sHp + pA0 * 128 + 2 * cg) = make_float2(hn0, hn1);
            *(float2*)(sHp + pA1 * 128 + 2 * cg) = make_float2(hn2, hn3);
        }
        pair_bar(rq);

        // ---------------- Pass C: logits + log-softmax NLL ----------------
        unsigned long long cP = 0;
        const float* hc = sHp + rg * 128;
#pragma unroll
        for (int k4 = 0; k4 < 64; k4 += 4) {
            float4 A = *(const float4*)(hc + 2 * k4);
            float4 B = *(const float4*)(hc + 2 * k4 + 4);
            unsigned long long hp[4];
            hp[0] = pack2(A.x, A.y); hp[1] = pack2(A.z, A.w);
            hp[2] = pack2(B.x, B.y); hp[3] = pack2(B.z, B.w);
#pragma unroll
            for (int kk = 0; kk < 4; kk++) {
                unsigned long long wd = dup2(sWp[(k4 + kk) * 32 + v]);
                cP = fma2(hp[kk], wd, cP);
            }
        }
        float accC[2];
        unpack2(cP, accC[0], accC[1]);
#pragma unroll
        for (int r = 0; r < 2; r++) {
            int row = 2 * rg + r;
            float lg = accC[r] + bp;
            out[((long long)(b0 + row) * TT + t) * VV + v] = lg;
            int tgt = sCS[row * T1 + t + 1];
            float m = lg;
#pragma unroll
            for (int o = 16; o > 0; o >>= 1)
                m = fmaxf(m, __shfl_xor_sync(0xffffffffu, m, o));
            float s = __expf(lg - m);
#pragma unroll
            for (int o = 16; o > 0; o >>= 1)
                s += __shfl_xor_sync(0xffffffffu, s, o);
            float lt = __shfl_sync(0xffffffffu, lg, tgt);
            if (v == 0 && tgt != 0) {
                nllAcc += m + __logf(s) - lt;
                cntAcc += 1.f;
            }
        }
        // pass C reads only pair rg's sHp rows (written in pass B by this
        // same pair); next pass A likewise -> no barrier needed here.
    }

    // deterministic per-block loss partials
    if (v == 0) { sRed[rg] = nllAcc; sRed[8 + rg] = cntAcc; }
    __syncthreads();
    if (tid == 0) {
        float a = 0.f, c = 0.f;
#pragma unroll
        for (int i = 0; i < 8; i++) { a += sRed[i]; c += sRed[8 + i]; }
        g_part[blockIdx.x] = a;
        g_part[NBLK + blockIdx.x] = c;
    }
}

// -------------------------------------------------------------------------
// Kernel 4: final loss reduction (deterministic tree)
// -------------------------------------------------------------------------
__global__ void loss_kernel(float* __restrict__ out, long long out_size) {
    __shared__ float sa[NBLK], sc[NBLK];
    int tid = threadIdx.x;
    sa[tid] = g_part[tid];
    sc[tid] = g_part[NBLK + tid];
    __syncthreads();
    for (int s = NBLK / 2; s > 0; s >>= 1) {
        if (tid < s) { sa[tid] += sa[tid + s]; sc[tid] += sc[tid + s]; }
        __syncthreads();
    }
    if (tid == 0 && out_size > (long long)BB * TT * VV)
        out[out_size - 1] = sa[0] / fmaxf(sc[0], 1.f);
}

// -------------------------------------------------------------------------
extern "C" void kernel_launch(void* const* d_in, const int* in_sizes, int n_in,
                              void* d_out, int out_size) {
    const float* phon  = (const float*)d_in[0];
    const void*  cs    = d_in[1];
    const float* emb   = (const float*)d_in[2];
    const float* Wrx   = (const float*)d_in[3];
    const float* brx   = (const float*)d_in[4];
    const float* Wrh   = (const float*)d_in[5];
    const float* brh   = (const float*)d_in[6];
    const float* Wzx   = (const float*)d_in[7];
    const float* bzx   = (const float*)d_in[8];
    const float* Wzh   = (const float*)d_in[9];
    const float* bzh   = (const float*)d_in[10];
    const float* Whx   = (const float*)d_in[11];
    const float* bhx   = (const float*)d_in[12];
    const float* Whh   = (const float*)d_in[13];
    const float* bhh   = (const float*)d_in[14];
    const float* Wproj = (const float*)d_in[15];
    const float* bproj = (const float*)d_in[16];
    float* out = (float*)d_out;

    (void)cudaFuncSetAttribute(gru_kernel,
                               cudaFuncAttributeMaxDynamicSharedMemorySize,
                               SMEM_BYTES);

    detect_kernel<<<1, 1024>>>((const int*)cs, BB * T1);
    convert_kernel<<<(BB * T1 + 255) / 256, 256>>>(cs);
    table_kernel<<<24, 256>>>(emb, Wrx, Wzx, Whx);
    phonb_kernel<<<(3 * BB * 32 + 255) / 256, 256>>>(phon, Wrx, Wzx, Whx,
                                                     brx, brh, bzx, bzh, bhx, bhh);
    gru_kernel<<<NBLK, 256, SMEM_BYTES>>>(Wrh, Wzh, Whh, Wproj, bproj, out);
    loss_kernel<<<1, 256>>>(out, (long long)out_size);
}